// round 4
// baseline (speedup 1.0000x reference)
#include <cuda_runtime.h>
#include <cstdint>

#define Bm   32
#define Dm   2560
#define Em   5120
#define RK   160
#define STn  16
#define BE   (Bm*Em)
#define BD   (Bm*Dm)
#define KS_IN   16
#define KS_OUT  32
#define KS_DBC  80

typedef unsigned long long ull;

// -------- scratch ----------
__device__ float g_p_ssm[KS_IN * BE];
__device__ float g_p_mlp[KS_IN * BE];
__device__ float g_xt   [BE];
__device__ float g_res  [BE];
__device__ float g_dbcp [KS_DBC * Bm * 192];
__device__ float g_dbc  [Bm * 192];
__device__ float g_z    [BE];
__device__ float g_p_out[KS_OUT * BD];

// -------- f32x2 helpers ----------
__device__ __forceinline__ ull pack2(float x, float y) {
    ull r;
    asm("mov.b64 %0, {%1,%2};" : "=l"(r) : "f"(x), "f"(y));
    return r;
}
__device__ __forceinline__ void fma2(ull& d, ull a, ull b) {
    asm("fma.rn.f32x2 %0, %1, %2, %0;" : "+l"(d) : "l"(a), "l"(b));
}
__device__ __forceinline__ float2 unpack2(ull v) {
    float2 r;
    asm("mov.b64 {%0,%1}, %2;" : "=f"(r.x), "=f"(r.y) : "l"(v));
    return r;
}
__device__ __forceinline__ float silu_f(float v) {
    return v * (1.0f / (1.0f + expf(-v)));
}

// ---------------------------------------------------------------------------
// gemm32c: 32-row GEMM, N-tile 256, 256 threads (8 warps), micro 4x8 f32x2.
// Register-prefetch global->smem pipeline; all smem reads LDS.128.
// ---------------------------------------------------------------------------
template <int KTOT, int KSPLIT, int NCOLS, int XSTRIDE, int SRC, int DST>
__global__ __launch_bounds__(256, 2)
void gemm32c(const float* __restrict__ X, const float* __restrict__ W) {
    __shared__ float Ws[16][256];      // 16 KB
    __shared__ ull   Xs[16][34];       // 4.3 KB, (v,v) packed

    const float* Xp = (SRC == 0) ? X : g_z;
    float* part = (DST == 0) ? g_p_ssm : (DST == 1) ? g_p_mlp : g_p_out;

    const int t  = threadIdx.x;
    const int n0 = blockIdx.x * 256;
    constexpr int KPER = KTOT / KSPLIT;
    constexpr int NCH  = KPER / 16;
    const int kbase = blockIdx.y * KPER;
    const int cg = t & 31;        // 32 col-groups of 8 cols
    const int rg = t >> 5;        // 8 row-groups of 4 rows
    const int b0 = rg * 4;

    ull acc[4][4];
#pragma unroll
    for (int j = 0; j < 4; j++)
#pragma unroll
        for (int q = 0; q < 4; q++) acc[j][q] = 0ULL;

    float4 wreg[4];
    float  xreg[2];

    // prefetch chunk 0
    {
        const int kg = kbase;
#pragma unroll
        for (int r = 0; r < 4; r++) {
            int f = t + r * 256, row = f >> 6, c4 = f & 63;
            wreg[r] = *reinterpret_cast<const float4*>(
                &W[(size_t)(kg + row) * NCOLS + n0 + c4 * 4]);
        }
#pragma unroll
        for (int r = 0; r < 2; r++) {
            int i = t + r * 256, b = i >> 4, kk = i & 15;
            xreg[r] = Xp[b * XSTRIDE + kg + kk];
        }
    }

    for (int c = 0; c < NCH; c++) {
        // stage current chunk to smem
#pragma unroll
        for (int r = 0; r < 4; r++) {
            int f = t + r * 256, row = f >> 6, c4 = f & 63;
            *reinterpret_cast<float4*>(&Ws[row][c4 * 4]) = wreg[r];
        }
#pragma unroll
        for (int r = 0; r < 2; r++) {
            int i = t + r * 256, b = i >> 4, kk = i & 15;
            Xs[kk][b] = pack2(xreg[r], xreg[r]);
        }
        // issue next chunk's global loads (latency overlapped with compute)
        if (c + 1 < NCH) {
            const int kg = kbase + (c + 1) * 16;
#pragma unroll
            for (int r = 0; r < 4; r++) {
                int f = t + r * 256, row = f >> 6, c4 = f & 63;
                wreg[r] = *reinterpret_cast<const float4*>(
                    &W[(size_t)(kg + row) * NCOLS + n0 + c4 * 4]);
            }
#pragma unroll
            for (int r = 0; r < 2; r++) {
                int i = t + r * 256, b = i >> 4, kk = i & 15;
                xreg[r] = Xp[b * XSTRIDE + kg + kk];
            }
        }
        __syncthreads();
#pragma unroll
        for (int kk = 0; kk < 16; kk++) {
            ulonglong2 w01 = *reinterpret_cast<const ulonglong2*>(&Ws[kk][cg * 8]);
            ulonglong2 w23 = *reinterpret_cast<const ulonglong2*>(&Ws[kk][cg * 8 + 4]);
            ulonglong2 x01 = *reinterpret_cast<const ulonglong2*>(&Xs[kk][b0]);
            ulonglong2 x23 = *reinterpret_cast<const ulonglong2*>(&Xs[kk][b0 + 2]);
            ull xs[4] = {x01.x, x01.y, x23.x, x23.y};
#pragma unroll
            for (int j = 0; j < 4; j++) {
                fma2(acc[j][0], xs[j], w01.x);
                fma2(acc[j][1], xs[j], w01.y);
                fma2(acc[j][2], xs[j], w23.x);
                fma2(acc[j][3], xs[j], w23.y);
            }
        }
        __syncthreads();
    }
#pragma unroll
    for (int j = 0; j < 4; j++) {
        float2 a0 = unpack2(acc[j][0]);
        float2 a1 = unpack2(acc[j][1]);
        float2 a2 = unpack2(acc[j][2]);
        float2 a3 = unpack2(acc[j][3]);
        float* dst = &part[((size_t)blockIdx.y * Bm + b0 + j) * NCOLS + n0 + cg * 8];
        *reinterpret_cast<float4*>(dst)     = make_float4(a0.x, a0.y, a1.x, a1.y);
        *reinterpret_cast<float4*>(dst + 4) = make_float4(a2.x, a2.y, a3.x, a3.y);
    }
}

// ---------------------------------------------------------------------------
// dbc GEMM: xt(32,5120) @ Wx(5120,192). N-tile 64, 128 threads, micro 4x4.
// grid (3, KS_DBC=80), KPER = 64 -> 2 chunks of 32.
// ---------------------------------------------------------------------------
__global__ __launch_bounds__(128)
void dbc_gemm_kernel(const float* __restrict__ Wx) {
    __shared__ ull Xs2[32][34];
    __shared__ ull Ws2[32][32];

    const int t  = threadIdx.x;
    const int n0 = blockIdx.x * 64;
    constexpr int KPER = Em / KS_DBC;  // 64
    const int kbase = blockIdx.y * KPER;
    const int cg = t & 15;
    const int rg = t >> 4;
    const int b0 = rg * 4;
    const int qu = cg * 2;

    ull acc[4][2];
#pragma unroll
    for (int j = 0; j < 4; j++) { acc[j][0] = 0ULL; acc[j][1] = 0ULL; }

    for (int kc = 0; kc < KPER; kc += 32) {
        const int kg = kbase + kc;
#pragma unroll
        for (int i = t; i < 1024; i += 128) {
            int b = i >> 5, kk = i & 31;
            float v = g_xt[b * Em + kg + kk];
            Xs2[kk][b] = pack2(v, v);
        }
#pragma unroll
        for (int i = t; i < 512; i += 128) {
            int kk = i >> 4, c4 = i & 15;
            float4 w = *reinterpret_cast<const float4*>(
                &Wx[(size_t)(kg + kk) * 192 + n0 + c4 * 4]);
            Ws2[kk][c4 * 2]     = pack2(w.x, w.y);
            Ws2[kk][c4 * 2 + 1] = pack2(w.z, w.w);
        }
        __syncthreads();
#pragma unroll
        for (int kk = 0; kk < 32; kk++) {
            ulonglong2 w = *reinterpret_cast<const ulonglong2*>(&Ws2[kk][qu]);
            ulonglong2 x01 = *reinterpret_cast<const ulonglong2*>(&Xs2[kk][b0]);
            ulonglong2 x23 = *reinterpret_cast<const ulonglong2*>(&Xs2[kk][b0 + 2]);
            ull xs[4] = {x01.x, x01.y, x23.x, x23.y};
#pragma unroll
            for (int j = 0; j < 4; j++) {
                fma2(acc[j][0], xs[j], w.x);
                fma2(acc[j][1], xs[j], w.y);
            }
        }
        __syncthreads();
    }
#pragma unroll
    for (int j = 0; j < 4; j++) {
        float2 a0 = unpack2(acc[j][0]);
        float2 a1 = unpack2(acc[j][1]);
        *reinterpret_cast<float4*>(
            &g_dbcp[((size_t)blockIdx.y * Bm + b0 + j) * 192 + n0 + cg * 4]) =
            make_float4(a0.x, a0.y, a1.x, a1.y);
    }
}

// ---------------------------------------------------------------------------
__global__ __launch_bounds__(256)
void conv_silu_kernel(const float* __restrict__ conv_w,
                      const float* __restrict__ conv_b,
                      const float* __restrict__ conv_states) {
    int idx = blockIdx.x * 256 + threadIdx.x;
    float xssm = 0.0f, xmlp = 0.0f;
#pragma unroll
    for (int ks = 0; ks < KS_IN; ks++) {
        xssm += g_p_ssm[idx + ks * BE];
        xmlp += g_p_mlp[idx + ks * BE];
    }
    float c = conv_b[idx];
    c += conv_states[idx]          * conv_w[idx];
    c += conv_states[idx + BE]     * conv_w[idx + BE];
    c += conv_states[idx + 2 * BE] * conv_w[idx + 2 * BE];
    c += xssm                      * conv_w[idx + 3 * BE];
    g_xt[idx]  = silu_f(c);
    g_res[idx] = silu_f(xmlp);
}

__global__ void dbc_reduce_kernel() {
    int i = blockIdx.x * 256 + threadIdx.x;  // [0, 6144)
    float s = 0.0f;
#pragma unroll
    for (int ks = 0; ks < KS_DBC; ks++) s += g_dbcp[ks * Bm * 192 + i];
    g_dbc[i] = s;
}

// ---------------------------------------------------------------------------
__global__ __launch_bounds__(256)
void ssm_kernel(const float* __restrict__ W_dt,
                const float* __restrict__ dt_bias,
                const float* __restrict__ A_log,
                const float* __restrict__ Dv,
                const float* __restrict__ h) {
    int gid = blockIdx.x * 256 + threadIdx.x;  // [0, 16*Em)
    int e  = gid % Em;
    int b0 = (gid / Em) * 2;

    float dt0 = 0.0f, dt1 = 0.0f;
#pragma unroll 8
    for (int k = 0; k < RK; k++) {
        float wd = W_dt[(size_t)k * Em + e];
        dt0 += g_dbc[b0 * 192 + k] * wd;
        dt1 += g_dbc[(b0 + 1) * 192 + k] * wd;
    }

    float bias = dt_bias[e];
    float dval = Dv[e];
    float An[STn];
#pragma unroll
    for (int n = 0; n < STn; n++) An[n] = -expf(A_log[(size_t)e * STn + n]);

    float dts[2] = {dt0, dt1};
#pragma unroll
    for (int j = 0; j < 2; j++) {
        int b = b0 + j;
        float s = dts[j] + bias;
        float dt = (s > 20.0f) ? s : log1pf(expf(s));
        float xt = g_xt[b * Em + e];
        const float* hb = &h[((size_t)b * Em + e) * STn];
        float y = 0.0f;
#pragma unroll
        for (int n = 0; n < STn; n++) {
            float Bv = g_dbc[b * 192 + 160 + n];
            float Cv = g_dbc[b * 192 + 176 + n];
            float dA = expf(dt * An[n]);
            float hn = hb[n] * dA + dt * Bv * xt;
            y += hn * Cv;
        }
        y += dval * xt;
        g_z[b * Em + e] = y * g_res[b * Em + e];
    }
}

__global__ void out_reduce_kernel(float* __restrict__ out) {
    int i = blockIdx.x * 256 + threadIdx.x;  // [0, BD)
    float s = 0.0f;
#pragma unroll
    for (int ks = 0; ks < KS_OUT; ks++) s += g_p_out[ks * BD + i];
    out[i] = s;
}

// ---------------------------------------------------------------------------
extern "C" void kernel_launch(void* const* d_in, const int* in_sizes, int n_in,
                              void* d_out, int out_size) {
    const float* x        = (const float*)d_in[0];
    const float* W_in_ssm = (const float*)d_in[1];
    const float* W_in_mlp = (const float*)d_in[2];
    const float* W_out    = (const float*)d_in[3];
    const float* conv_w   = (const float*)d_in[4];
    const float* conv_b   = (const float*)d_in[5];
    const float* conv_st  = (const float*)d_in[6];
    const float* Wx       = (const float*)d_in[7];
    const float* W_dt     = (const float*)d_in[8];
    const float* dt_bias  = (const float*)d_in[9];
    const float* A_log    = (const float*)d_in[10];
    const float* Dvec     = (const float*)d_in[11];
    const float* h        = (const float*)d_in[12];
    float* out = (float*)d_out;

    gemm32c<2560, KS_IN, 5120, 2560, 0, 0><<<dim3(20, KS_IN), 256>>>(x, W_in_ssm);
    gemm32c<2560, KS_IN, 5120, 2560, 0, 1><<<dim3(20, KS_IN), 256>>>(x, W_in_mlp);
    conv_silu_kernel<<<BE / 256, 256>>>(conv_w, conv_b, conv_st);
    dbc_gemm_kernel<<<dim3(3, KS_DBC), 128>>>(Wx);
    dbc_reduce_kernel<<<24, 256>>>();
    ssm_kernel<<<320, 256>>>(W_dt, dt_bias, A_log, Dvec, h);
    gemm32c<5120, KS_OUT, 2560, 5120, 1, 2><<<dim3(10, KS_OUT), 256>>>(nullptr, W_out);
    out_reduce_kernel<<<BD / 256, 256>>>(out);
}